// round 6
// baseline (speedup 1.0000x reference)
#include <cuda_runtime.h>
#include <cuda_bf16.h>
#include <cstdint>

// Problem constants
#define B_     2
#define L2_    4
#define N2_    2048
#define L1_    9
#define N1_    8192
#define CIN_   128
#define CT_    128
#define CS_    256
#define CORIG_ 64
#define KD3_   192   // CT_ + CORIG_

typedef __nv_bfloat16 bf16;

// Scratch (static device globals — no runtime allocation)
__device__ float g_tt [B_*L2_*3*N2_*CT_];                 // stage-2 out, n-major [z][n][o] fp32
__device__ __align__(128) float4 g_seed[B_*L2_*N2_];      // (x,y,z,|s|^2)
__device__ __align__(128) bf16 g_wt0h[3*CT_*CIN_];
__device__ __align__(128) bf16 g_wt0l[3*CT_*CIN_];
__device__ __align__(128) bf16 g_wt1h[3*CT_*CT_];
__device__ __align__(128) bf16 g_wt1l[3*CT_*CT_];
__device__ __align__(128) bf16 g_whi [CS_*KD3_];
__device__ __align__(128) bf16 g_wlo [CS_*KD3_];
__device__ __align__(128) bf16 g_fh  [(size_t)B_*L2_*CIN_*N2_];
__device__ __align__(128) bf16 g_fl  [(size_t)B_*L2_*CIN_*N2_];
__device__ __align__(128) bf16 g_hh  [(size_t)B_*L2_*3*CT_*N2_];
__device__ __align__(128) bf16 g_hl  [(size_t)B_*L2_*3*CT_*N2_];
__device__ __align__(128) bf16 g_bhi [(size_t)B_*L1_*N1_*KD3_];
__device__ __align__(128) bf16 g_blo [(size_t)B_*L1_*N1_*KD3_];

__device__ __forceinline__ uint32_t smem_u32(const void* p) {
    uint32_t a;
    asm("{ .reg .u64 t; cvta.to.shared.u64 t, %1; cvt.u32.u64 %0, t; }"
        : "=r"(a) : "l"(p));
    return a;
}
__device__ __forceinline__ void ldmx4(uint32_t* r, uint32_t addr) {
    asm volatile("ldmatrix.sync.aligned.m8n8.x4.shared.b16 {%0,%1,%2,%3}, [%4];"
                 : "=r"(r[0]), "=r"(r[1]), "=r"(r[2]), "=r"(r[3]) : "r"(addr));
}
__device__ __forceinline__ void ldmx4t(uint32_t* r, uint32_t addr) {
    asm volatile("ldmatrix.sync.aligned.m8n8.x4.trans.shared.b16 {%0,%1,%2,%3}, [%4];"
                 : "=r"(r[0]), "=r"(r[1]), "=r"(r[2]), "=r"(r[3]) : "r"(addr));
}
__device__ __forceinline__ void mma_bf16(float* d, const uint32_t* a,
                                         const uint32_t* b) {
    asm volatile("mma.sync.aligned.m16n8k16.row.col.f32.bf16.bf16.f32 "
                 "{%0,%1,%2,%3}, {%4,%5,%6,%7}, {%8,%9}, {%0,%1,%2,%3};"
                 : "+f"(d[0]), "+f"(d[1]), "+f"(d[2]), "+f"(d[3])
                 : "r"(a[0]), "r"(a[1]), "r"(a[2]), "r"(a[3]),
                   "r"(b[0]), "r"(b[1]));
}
__device__ __forceinline__ void split_bf16(float v, bf16& hi, bf16& lo) {
    hi = __float2bfloat16(v);
    lo = __float2bfloat16(v - __bfloat162float(hi));
}

// ---------------------------------------------------------------------------
// Prep: weight splits, feature split, OF transpose+split, seed float4
// ---------------------------------------------------------------------------
#define PREP_W   576
#define PREP_F   8192
#define PREP_OF  2304
#define PREP_S   64
__global__ __launch_bounds__(256) void k_prep(
    const float* __restrict__ Wt0, const float* __restrict__ Wt1,
    const float* __restrict__ Ws,  const float* __restrict__ F,
    const float* __restrict__ OF,  const float* __restrict__ xyzs)
{
    const int bx  = blockIdx.x;
    const int tid = threadIdx.x;
    if (bx < PREP_W) {
        int i = bx * 256 + tid;
        bf16 hi, lo;
        if (i < 49152) {
            split_bf16(Wt0[i], hi, lo);
            g_wt0h[i] = hi; g_wt0l[i] = lo;
        } else if (i < 98304) {
            int j = i - 49152;
            split_bf16(Wt1[j], hi, lo);
            g_wt1h[j] = hi; g_wt1l[j] = lo;
        } else {
            int j = i - 98304;
            split_bf16(Ws[j], hi, lo);
            g_whi[j] = hi; g_wlo[j] = lo;
        }
    } else if (bx < PREP_W + PREP_F) {
        size_t i = (size_t)(bx - PREP_W) * 256 + tid;
        bf16 hi, lo;
        split_bf16(F[i], hi, lo);
        g_fh[i] = hi; g_fl[i] = lo;
    } else if (bx < PREP_W + PREP_F + PREP_OF) {
        const int rb = bx - PREP_W - PREP_F;
        const int bt = rb >> 7;
        const int nb = (rb & 127) * 64;
        __shared__ bf16 sh[64][65], sl[64][65];
#pragma unroll
        for (int i = 0; i < 16; i++) {
            int idx = tid + i * 256;
            int c = idx >> 6, n = idx & 63;
            bf16 hi, lo;
            split_bf16(OF[((size_t)bt * CORIG_ + c) * N1_ + nb + n], hi, lo);
            sh[c][n] = hi; sl[c][n] = lo;
        }
        __syncthreads();
#pragma unroll
        for (int i = 0; i < 16; i++) {
            int idx = tid + i * 256;
            int n = idx >> 6, c = idx & 63;
            size_t d = ((size_t)bt * N1_ + nb + n) * KD3_ + CT_ + c;
            g_bhi[d] = sh[c][n];
            g_blo[d] = sl[c][n];
        }
    } else {
        int i = (bx - PREP_W - PREP_F - PREP_OF) * 256 + tid;  // 0..16383
        float x = xyzs[i * 3], y = xyzs[i * 3 + 1], z = xyzs[i * 3 + 2];
        g_seed[i] = make_float4(x, y, z, x * x + y * y + z * z);
    }
}

// ---------------------------------------------------------------------------
// HMMA GEMM for stages 1 & 2 (split-3 bf16)
// ---------------------------------------------------------------------------
template<int STAGE>
__global__ __launch_bounds__(256) void k_hgemm()
{
    __shared__ __align__(128) char sA[128 * 128];
    __shared__ __align__(128) char sB[64 * 256];

    const int tid  = threadIdx.x;
    const int wid  = tid >> 5, lane = tid & 31;
    const int z    = blockIdx.z;
    const int nb   = blockIdx.x * 128;
    const int m_w  = (wid & 3) * 32;
    const int n_w  = (wid >> 2) * 64;

    const bf16* Ah;
    const bf16* Al;
    const bf16* Bh;
    const bf16* Bl;
    if (STAGE == 1) {
        Ah = g_wt0h + (z % 3) * CT_ * CIN_;
        Al = g_wt0l + (z % 3) * CT_ * CIN_;
        Bh = g_fh + (size_t)(z / 3) * CIN_ * N2_;
        Bl = g_fl + (size_t)(z / 3) * CIN_ * N2_;
    } else {
        Ah = g_wt1h + (z % 3) * CT_ * CT_;
        Al = g_wt1l + (z % 3) * CT_ * CT_;
        Bh = g_hh + (size_t)z * CT_ * N2_;
        Bl = g_hl + (size_t)z * CT_ * N2_;
    }

    const uint32_t sa_b = smem_u32(sA);
    const uint32_t sb_b = smem_u32(sB);

    float d[2][8][4];
#pragma unroll
    for (int mt = 0; mt < 2; mt++)
#pragma unroll
        for (int nt = 0; nt < 8; nt++)
#pragma unroll
            for (int r = 0; r < 4; r++) d[mt][nt][r] = 0.f;

    for (int chunk = 0; chunk < 6; chunk++) {
        const int p  = chunk >> 1;
        const int k0 = (chunk & 1) * 64;
        const bf16* Asrc = (p < 2) ? Ah : Al;
        const bf16* Bsrc = (p == 1) ? Bl : Bh;
        __syncthreads();
#pragma unroll
        for (int i = 0; i < 4; i++) {
            int idx = tid + i * 256;
            int m = idx >> 3, u = idx & 7;
            uint4 v = *(const uint4*)(Asrc + m * 128 + k0 + u * 8);
            *(uint4*)(sA + m * 128 + ((u * 16) ^ ((m & 7) << 4))) = v;
        }
#pragma unroll
        for (int i = 0; i < 4; i++) {
            int idx = tid + i * 256;
            int kr = idx >> 4, u = idx & 15;
            uint4 v = *(const uint4*)(Bsrc + (size_t)(k0 + kr) * N2_ + nb + u * 8);
            *(uint4*)(sB + kr * 256 + ((u * 16) ^ ((kr & 7) << 4))) = v;
        }
        __syncthreads();

#pragma unroll
        for (int ks = 0; ks < 4; ks++) {
            uint32_t a[2][4];
#pragma unroll
            for (int mt = 0; mt < 2; mt++) {
                int m = m_w + mt * 16 + (lane & 15);
                uint32_t addr = sa_b + m * 128 +
                    (((uint32_t)(ks * 32 + (lane >> 4) * 16)) ^ ((m & 7) << 4));
                ldmx4(a[mt], addr);
            }
            uint32_t b[4][4];
#pragma unroll
            for (int pr = 0; pr < 4; pr++) {
                int kr = ks * 16 + (lane & 15);
                uint32_t nc = (uint32_t)(n_w + pr * 16 + (lane >> 4) * 8) * 2;
                uint32_t addr = sb_b + kr * 256 + (nc ^ ((kr & 7) << 4));
                ldmx4t(b[pr], addr);
            }
#pragma unroll
            for (int mt = 0; mt < 2; mt++)
#pragma unroll
                for (int nt = 0; nt < 8; nt++)
                    mma_bf16(d[mt][nt], a[mt], &b[nt >> 1][(nt & 1) * 2]);
        }
    }

    const int qrow = lane >> 2, qcol = (lane & 3) * 2;
    if (STAGE == 1) {
        bf16* Hh = g_hh + (size_t)z * CT_ * N2_;
        bf16* Hl = g_hl + (size_t)z * CT_ * N2_;
#pragma unroll
        for (int mt = 0; mt < 2; mt++) {
#pragma unroll
            for (int half = 0; half < 2; half++) {
                int row = m_w + mt * 16 + half * 8 + qrow;
#pragma unroll
                for (int nt = 0; nt < 8; nt++) {
                    int col = nb + n_w + nt * 8 + qcol;
                    float x = fmaxf(d[mt][nt][half * 2],     0.f);
                    float y = fmaxf(d[mt][nt][half * 2 + 1], 0.f);
                    bf16 xh, xl, yh, yl;
                    split_bf16(x, xh, xl);
                    split_bf16(y, yh, yl);
                    __nv_bfloat162 vh; vh.x = xh; vh.y = yh;
                    __nv_bfloat162 vl; vl.x = xl; vl.y = yl;
                    *(__nv_bfloat162*)(Hh + (size_t)row * N2_ + col) = vh;
                    *(__nv_bfloat162*)(Hl + (size_t)row * N2_ + col) = vl;
                }
            }
        }
    } else {
        float* C = g_tt + (size_t)z * N2_ * CT_;
#pragma unroll
        for (int mt = 0; mt < 2; mt++) {
#pragma unroll
            for (int half = 0; half < 2; half++) {
                int row = m_w + mt * 16 + half * 8 + qrow;
#pragma unroll
                for (int nt = 0; nt < 8; nt++) {
                    int col = nb + n_w + nt * 8 + qcol;
                    C[(size_t)col * CT_ + row]       = fmaxf(d[mt][nt][half * 2],     0.f);
                    C[(size_t)(col + 1) * CT_ + row] = fmaxf(d[mt][nt][half * 2 + 1], 0.f);
                }
            }
        }
    }
}

// ---------------------------------------------------------------------------
// KNN + interp fused, 512 threads:
//   phase 1: 2 threads per query scan contiguous halves of each 2048-seed
//            segment using d' = |s|^2 - 2 q.s (float4 seeds, 1 LDS.128/seed)
//   merge:   6-candidate (d,seq) lexicographic merge per query
//   phase 2: gather-interp, 4 queries per iteration
// ---------------------------------------------------------------------------
__global__ __launch_bounds__(512) void k_knn_interp(
    const float* __restrict__ oxyzs)
{
    const int bt  = blockIdx.y;
    const int bq  = bt / 9;
    const int t1  = bt % 9 + 1;
    const int qb  = blockIdx.x * 256;
    const int tid = threadIdx.x;
    const int ql  = tid >> 1;            // local query 0..255
    const int hf  = tid & 1;             // which half of seeds

    int t2s[2], ks[2], nseg = 0;
    if ((t1 & 1) == 0) { t2s[0] = t1 / 2 - 1; ks[0] = 1; nseg = 1; }
    else {
        int p = (t1 - 1) >> 1;
        if (p - 1 >= 0) { t2s[nseg] = p - 1; ks[nseg] = 2; nseg++; }
        if (p <= 3)     { t2s[nseg] = p;     ks[nseg] = 0; nseg++; }
    }

    const float* q = oxyzs + ((size_t)bt * N1_ + qb + ql) * 3;
    const float qx = q[0], qy = q[1], qz = q[2];
    const float nx = -2.f * qx, ny = -2.f * qy, nz = -2.f * qz;
    const float qq = qx * qx + qy * qy + qz * qz;

    __shared__ float4 seed[2048];            // 32KB
    __shared__ float  cd[512 * 3];           // 6KB
    __shared__ int    co[512 * 3];           // 6KB
    __shared__ int    cs[512 * 3];           // 6KB
    __shared__ float  swt[256 * 3];          // 3KB
    __shared__ int    sof[256 * 3];          // 3KB

    float b0 = 3.4e38f, b1 = 3.4e38f, b2 = 3.4e38f;
    int   o0 = 0, o1 = 0, o2 = 0;
    int   s0 = 0, s1 = 0, s2 = 0;

    for (int s = 0; s < nseg; s++) {
        const float4* sp = g_seed + (bq * 4 + t2s[s]) * N2_;
        const int offbase = ((bq * 4 + t2s[s]) * 3 + ks[s]) * (N2_ * CT_);
        __syncthreads();
        for (int t = tid; t < 2048; t += 512) seed[t] = sp[t];
        __syncthreads();
        const int base = hf * 1024;
        const int seqb = s * 2048 + base;
#pragma unroll 4
        for (int t = 0; t < 1024; t++) {
            float4 v = seed[base + t];
            float d = fmaf(v.x, nx, fmaf(v.y, ny, fmaf(v.z, nz, v.w)));
            if (d < b2) {
                int off = offbase + (base + t) * CT_;
                int sq  = seqb + t;
                if (d < b1) {
                    b2 = b1; o2 = o1; s2 = s1;
                    if (d < b0) { b1 = b0; o1 = o0; s1 = s0;
                                  b0 = d;  o0 = off; s0 = sq; }
                    else        { b1 = d;  o1 = off; s1 = sq; }
                } else { b2 = d; o2 = off; s2 = sq; }
            }
        }
    }

    cd[tid * 3] = b0; cd[tid * 3 + 1] = b1; cd[tid * 3 + 2] = b2;
    co[tid * 3] = o0; co[tid * 3 + 1] = o1; co[tid * 3 + 2] = o2;
    cs[tid * 3] = s0; cs[tid * 3 + 1] = s1; cs[tid * 3 + 2] = s2;
    __syncthreads();

    if (hf == 0) {
        // merge own (b*/o*/s*) with neighbor (tid+1) by (d, seq)
        float ad[3] = {b0, b1, b2};
        int   ao[3] = {o0, o1, o2}, as_[3] = {s0, s1, s2};
        float bd[3] = {cd[(tid+1)*3], cd[(tid+1)*3+1], cd[(tid+1)*3+2]};
        int   bo[3] = {co[(tid+1)*3], co[(tid+1)*3+1], co[(tid+1)*3+2]};
        int   bs[3] = {cs[(tid+1)*3], cs[(tid+1)*3+1], cs[(tid+1)*3+2]};
        float md[3]; int mo[3];
        int i = 0, j = 0;
#pragma unroll
        for (int k = 0; k < 3; k++) {
            bool ta = (ad[i] < bd[j]) || (ad[i] == bd[j] && as_[i] < bs[j]);
            if (ta) { md[k] = ad[i]; mo[k] = ao[i]; i++; }
            else    { md[k] = bd[j]; mo[k] = bo[j]; j++; }
        }
        float w0 = 1.f / (md[0] + qq + 1e-8f);
        float w1 = 1.f / (md[1] + qq + 1e-8f);
        float w2 = 1.f / (md[2] + qq + 1e-8f);
        float si = 1.f / (w0 + w1 + w2);
        swt[ql * 3]     = w0 * si;
        swt[ql * 3 + 1] = w1 * si;
        swt[ql * 3 + 2] = w2 * si;
        sof[ql * 3]     = mo[0];
        sof[ql * 3 + 1] = mo[1];
        sof[ql * 3 + 2] = mo[2];
    }
    __syncthreads();

    // phase 2: 4 queries per iteration
    const int sub = tid >> 7;            // 0..3
    const int c   = tid & 127;
#pragma unroll 2
    for (int it = 0; it < 64; it++) {
        int qq2 = it + sub * 64;
        float w0 = swt[qq2 * 3], w1 = swt[qq2 * 3 + 1], w2 = swt[qq2 * 3 + 2];
        int   p0 = sof[qq2 * 3], p1 = sof[qq2 * 3 + 1], p2 = sof[qq2 * 3 + 2];
        float v = w0 * g_tt[p0 + c] + w1 * g_tt[p1 + c] + w2 * g_tt[p2 + c];
        bf16 hi, lo;
        split_bf16(v, hi, lo);
        size_t dd = ((size_t)bt * N1_ + qb + qq2) * KD3_ + c;
        g_bhi[dd] = hi;
        g_blo[dd] = lo;
    }
}

// ---------------------------------------------------------------------------
// Stage 3 via mma.sync bf16 split-3
// ---------------------------------------------------------------------------
__global__ __launch_bounds__(512, 1) void k_mma3(
    const float* __restrict__ gamma, const float* __restrict__ beta,
    const float* __restrict__ mean,  const float* __restrict__ var,
    float* __restrict__ out)
{
    __shared__ __align__(128) char sA[256 * 128];
    __shared__ __align__(128) char sB[128 * 128];

    const int tid  = threadIdx.x;
    const int wid  = tid >> 5, lane = tid & 31;
    const int bt   = blockIdx.z;
    const int nb   = blockIdx.x * 128;
    const int m_w  = (wid & 7) * 32;
    const int n_w  = (wid >> 3) * 64;

    const uint32_t sa_b = smem_u32(sA);
    const uint32_t sb_b = smem_u32(sB);
    const size_t   brow = ((size_t)bt * N1_ + nb) * KD3_;

    float d[2][8][4];
#pragma unroll
    for (int mt = 0; mt < 2; mt++)
#pragma unroll
        for (int nt = 0; nt < 8; nt++)
#pragma unroll
            for (int r = 0; r < 4; r++) d[mt][nt][r] = 0.f;

    for (int chunk = 0; chunk < 9; chunk++) {
        const int p  = chunk / 3;
        const int k0 = (chunk % 3) * 64;
        const bf16* Asrc = (p < 2) ? g_whi : g_wlo;
        const bf16* Bsrc = (p == 1) ? g_blo : g_bhi;
        __syncthreads();
#pragma unroll
        for (int i = 0; i < 4; i++) {
            int idx = tid + i * 512;
            int m = idx >> 3, part = idx & 7;
            uint4 v = *(const uint4*)(Asrc + m * KD3_ + k0 + part * 8);
            *(uint4*)(sA + m * 128 + ((part * 16) ^ ((m & 7) << 4))) = v;
        }
#pragma unroll
        for (int i = 0; i < 2; i++) {
            int idx = tid + i * 512;
            int n = idx >> 3, part = idx & 7;
            uint4 v = *(const uint4*)(Bsrc + brow + (size_t)n * KD3_ + k0 + part * 8);
            *(uint4*)(sB + n * 128 + ((part * 16) ^ ((n & 7) << 4))) = v;
        }
        __syncthreads();

#pragma unroll
        for (int ks = 0; ks < 4; ks++) {
            uint32_t a[2][4];
#pragma unroll
            for (int mt = 0; mt < 2; mt++) {
                int m = m_w + mt * 16 + (lane & 15);
                uint32_t addr = sa_b + m * 128 +
                    (((uint32_t)(ks * 32 + (lane >> 4) * 16)) ^ ((m & 7) << 4));
                ldmx4(a[mt], addr);
            }
            uint32_t b[4][4];
#pragma unroll
            for (int pr = 0; pr < 4; pr++) {
                int n = n_w + pr * 16 + (lane >> 4) * 8 + (lane & 7);
                uint32_t addr = sb_b + n * 128 +
                    (((uint32_t)(ks * 32 + ((lane >> 3) & 1) * 16)) ^ ((n & 7) << 4));
                ldmx4(b[pr], addr);
            }
#pragma unroll
            for (int mt = 0; mt < 2; mt++)
#pragma unroll
                for (int nt = 0; nt < 8; nt++)
                    mma_bf16(d[mt][nt], a[mt], &b[nt >> 1][(nt & 1) * 2]);
        }
    }

    const int qrow = lane >> 2, qcol = (lane & 3) * 2;
#pragma unroll
    for (int mt = 0; mt < 2; mt++) {
#pragma unroll
        for (int half = 0; half < 2; half++) {
            int m = m_w + mt * 16 + half * 8 + qrow;
            float sc = gamma[m] * rsqrtf(var[m] + 1e-5f);
            float bi = beta[m] - mean[m] * sc;
            float* Cp = out + ((size_t)bt * CS_ + m) * N1_ + nb + n_w;
#pragma unroll
            for (int nt = 0; nt < 8; nt++) {
                float x = fmaxf(d[mt][nt][half * 2]     * sc + bi, 0.f);
                float y = fmaxf(d[mt][nt][half * 2 + 1] * sc + bi, 0.f);
                *(float2*)&Cp[nt * 8 + qcol] = make_float2(x, y);
            }
        }
    }
}

// ---------------------------------------------------------------------------
extern "C" void kernel_launch(void* const* d_in, const int* in_sizes, int n_in,
                              void* d_out, int out_size)
{
    const float* xyzs   = (const float*)d_in[0];
    const float* oxyzs  = (const float*)d_in[1];
    const float* feats  = (const float*)d_in[2];
    const float* ofeats = (const float*)d_in[3];
    const float* Wt0    = (const float*)d_in[4];
    const float* Wt1    = (const float*)d_in[5];
    const float* Ws     = (const float*)d_in[6];
    const float* gamma  = (const float*)d_in[7];
    const float* beta   = (const float*)d_in[8];
    const float* mean   = (const float*)d_in[9];
    const float* var    = (const float*)d_in[10];

    const int NEWF = B_ * L1_ * CS_ * N1_;
    int ofs = out_size - NEWF;
    float* outF = (float*)d_out;
    if (ofs > 0) {
        cudaMemcpyAsync(d_out, d_in[1], (size_t)ofs * sizeof(float),
                        cudaMemcpyDeviceToDevice, 0);
        outF += ofs;
    }

    k_prep<<<PREP_W + PREP_F + PREP_OF + PREP_S, 256>>>(Wt0, Wt1, Ws, feats,
                                                        ofeats, xyzs);
    k_hgemm<1><<<dim3(16, 1, 24), 256>>>();
    k_hgemm<2><<<dim3(16, 1, 24), 256>>>();
    k_knn_interp<<<dim3(32, 18), 512>>>(oxyzs);
    k_mma3<<<dim3(64, 1, 18), 512>>>(gamma, beta, mean, var, outF);
}